// round 10
// baseline (speedup 1.0000x reference)
#include <cuda_runtime.h>
#include <stdint.h>

// RVAEModel: out[b, c, g] = weight[idx[b, g], c]
//   idx:    [256, 64]  (int32 OR int64 — detected by tiny kernel)
//   weight: fp32 [1024, 1024]
//   out:    fp32 [256, 1024, 8, 8] (= [256, 1024, 64])
//
// Block = (b, 256-wide c-span) = 8 subtiles of 32 c. 128 threads. Grid 1024
// ~ one full wave at 24KB smem/block.
// Per subtile: cp.async gather -> swizzled tin (2x8KB ping-pong)
//   -> LDS.128 x4 -> register 4x4 transpose (held in regs)
//   -> STS half0 (16c) -> 4KB TMA bulk store -> STS half1 -> 4KB TMA store.
// gather(h+2) is issued ONLY after the post-LDS barrier (fixes R9 race).
// tout reuse is guarded by bulk.wait_group.read 1 (allows exactly the one
// in-flight group that reads the OTHER half-buffer).

static constexpr int BS = 256;
static constexpr int M  = 64;    // tokens per sample (g)
static constexpr int C  = 1024;  // channels
static constexpr int NT = 8;     // subtiles per block
static constexpr int SC = 32;    // subtile c-width

__device__ int g_idx_is64; // 1 if indices buffer is int64, 0 if int32

// Indices are in [0, 1024). If buffer is LE int64, odd 32-bit words of the
// first 64 indices are all zero; for int32 data P = (1/1024)^64 ~ 0.
// Reads 128 words — in-bounds either way.
__global__ void detect_idx_dtype(const unsigned int* __restrict__ idx_words)
{
    unsigned int acc = 0;
    #pragma unroll
    for (int i = 0; i < 64; i++) acc |= idx_words[2 * i + 1];
    g_idx_is64 = (acc == 0) ? 1 : 0;
}

__global__ __launch_bounds__(128)
void rvae_gather_transpose(const void*  __restrict__ idx_raw,
                           const float* __restrict__ w,
                           float*       __restrict__ out)
{
    const int b   = blockIdx.y;
    const int cqb = blockIdx.x * (NT * SC); // block base channel (256-span)
    const int t   = threadIdx.x;            // 128 threads

    __shared__ __align__(128) float4 tin[2][M * 8];      // 2 x 8KB, swizzled
    __shared__ __align__(128) float  tout[2][16 * M];    // 2 x 4KB half-buffers

    // Gather lanes: c4 = t&7 (float4 col), gb = t>>3 (0..15), g = gb + 16i.
    const int c4 = t & 7;
    const int gb = t >> 3;
    int row[4];
    if (g_idx_is64) {
        #pragma unroll
        for (int i = 0; i < 4; i++)
            row[i] = (int)reinterpret_cast<const long long*>(idx_raw)[b * M + gb + 16 * i];
    } else {
        #pragma unroll
        for (int i = 0; i < 4; i++)
            row[i] = reinterpret_cast<const int*>(idx_raw)[b * M + gb + 16 * i];
    }

    auto gather = [&](int h) {
        const int c0 = cqb + SC * h;
        #pragma unroll
        for (int i = 0; i < 4; i++) {
            const int g = gb + 16 * i;
            const float*   src = w + (size_t)row[i] * C + c0 + (c4 << 2);
            const uint32_t dst = (uint32_t)__cvta_generic_to_shared(
                &tin[h & 1][g * 8 + (c4 ^ ((g >> 2) & 7))]);
            asm volatile("cp.async.cg.shared.global [%0], [%1], 16;"
                         :: "r"(dst), "l"(src) : "memory");
        }
        asm volatile("cp.async.commit_group;" ::: "memory");
    };

    gather(0);
    gather(1);

    // Transpose unit: 4g x 4c. ub = g-quad (0..15), uc = c-quad (0..7).
    const int ub = t & 15;
    const int uc = t >> 4;
    const int sc = uc ^ (ub & 7);  // swizzled tin column ((4ub+k)>>2 == ub)
    const int half = uc >> 2;      // which 16-c half this thread stores
    const int ch   = (uc & 3);     // c-quad within half

    #pragma unroll
    for (int h = 0; h < NT; h++) {
        if (h < NT - 1)
            asm volatile("cp.async.wait_group 1;" ::: "memory");
        else
            asm volatile("cp.async.wait_group 0;" ::: "memory");
        // Before reusing tout[0]: allow exactly the 1 pending group that
        // reads tout[1] (committed at h-1); the group reading tout[0] drains.
        if (t == 0 && h > 0)
            asm volatile("cp.async.bulk.wait_group.read 1;" ::: "memory");
        __syncthreads();

        // Full 32-c transpose into registers.
        const float4* ti = tin[h & 1];
        const float4 r0 = ti[(4 * ub + 0) * 8 + sc];
        const float4 r1 = ti[(4 * ub + 1) * 8 + sc];
        const float4 r2 = ti[(4 * ub + 2) * 8 + sc];
        const float4 r3 = ti[(4 * ub + 3) * 8 + sc];
        const float4 o0 = {r0.x, r1.x, r2.x, r3.x};
        const float4 o1 = {r0.y, r1.y, r2.y, r3.y};
        const float4 o2 = {r0.z, r1.z, r2.z, r3.z};
        const float4 o3 = {r0.w, r1.w, r2.w, r3.w};

        float* ot = tout[half] + 4 * ub;
        const size_t obase = (size_t)b * (C * M) + (size_t)(cqb + SC * h) * M;

        // ---- half 0 (threads with half==0 store; 16c = 4KB) ----
        if (half == 0) {
            *reinterpret_cast<float4*>(ot + (4 * ch + 0) * M) = o0;
            *reinterpret_cast<float4*>(ot + (4 * ch + 1) * M) = o1;
            *reinterpret_cast<float4*>(ot + (4 * ch + 2) * M) = o2;
            *reinterpret_cast<float4*>(ot + (4 * ch + 3) * M) = o3;
        }
        __syncthreads(); // ALL threads' LDS of tin[h&1] complete here

        // Safe now: refill tin[h&1] for subtile h+2 (overlaps TMA + STS half1)
        if (h + 2 < NT) gather(h + 2);

        if (t == 0) {
            asm volatile("fence.proxy.async.shared::cta;" ::: "memory");
            const uint32_t src = (uint32_t)__cvta_generic_to_shared(tout[0]);
            asm volatile(
                "cp.async.bulk.global.shared::cta.bulk_group [%0], [%1], %2;"
                :: "l"(out + obase), "r"(src), "r"(16 * M * 4) : "memory");
            asm volatile("cp.async.bulk.commit_group;" ::: "memory");
            // Before reusing tout[1]: allow the 1 pending group (tout[0], just
            // committed); the group reading tout[1] (from h-1) drains.
            if (h > 0)
                asm volatile("cp.async.bulk.wait_group.read 1;" ::: "memory");
        }
        __syncthreads();

        // ---- half 1 ----
        if (half == 1) {
            *reinterpret_cast<float4*>(ot + (4 * ch + 0) * M) = o0;
            *reinterpret_cast<float4*>(ot + (4 * ch + 1) * M) = o1;
            *reinterpret_cast<float4*>(ot + (4 * ch + 2) * M) = o2;
            *reinterpret_cast<float4*>(ot + (4 * ch + 3) * M) = o3;
        }
        __syncthreads();
        if (t == 0) {
            asm volatile("fence.proxy.async.shared::cta;" ::: "memory");
            const uint32_t src = (uint32_t)__cvta_generic_to_shared(tout[1]);
            asm volatile(
                "cp.async.bulk.global.shared::cta.bulk_group [%0], [%1], %2;"
                :: "l"(out + obase + 16 * M), "r"(src), "r"(16 * M * 4) : "memory");
            asm volatile("cp.async.bulk.commit_group;" ::: "memory");
        }
    }

    // Keep CTA (and smem) alive until the final TMA reads complete.
    if (t == 0)
        asm volatile("cp.async.bulk.wait_group.read 0;" ::: "memory");
}

extern "C" void kernel_launch(void* const* d_in, const int* in_sizes, int n_in,
                              void* d_out, int out_size)
{
    // indices: 16384 elements; weight: 1048576 elements (fp32)
    const void*  idx;
    const float* w;
    if (in_sizes[0] == BS * M) {
        idx = d_in[0];
        w   = (const float*)d_in[1];
    } else {
        idx = d_in[1];
        w   = (const float*)d_in[0];
    }

    detect_idx_dtype<<<1, 1>>>((const unsigned int*)idx);

    dim3 grid(C / (NT * SC), BS); // (4, 256) = 1024 blocks ~ one wave
    rvae_gather_transpose<<<grid, 128>>>(idx, w, (float*)d_out);
}

// round 12
// speedup vs baseline: 1.1007x; 1.1007x over previous
#include <cuda_runtime.h>
#include <stdint.h>

// RVAEModel: out[b, c, g] = weight[idx[b, g], c]
//   idx:    [256, 64]  (int32 OR int64 — detected by tiny kernel)
//   weight: fp32 [1024, 1024]
//   out:    fp32 [256, 1024, 8, 8] (= [256, 1024, 64])
//
// Block = (b, 256-wide c-span) = 8 subtiles of 32 c. 128 threads, grid 1024
// (single wave at 32KB smem/CTA). 4-deep cp.async ring, ONE barrier per
// subtile, EXACT wait-group accounting:
//   committed(h) = 4 + clamp(h-1,0,4); allow(h) = committed(h) - (h+1)
//   = {3,2,2,2,2,2,1,0} -> tile h is always complete before its LDS.
//   iter h: wait_group allow(h) -> syncthreads (publishes tile h, proves
//   tile h-1 consumed by all threads) -> gather(h+3) into (h-1)%4 ->
//   LDS.128 x4 -> register 4x4 transpose -> STG.128 x4 (coalesced).

static constexpr int BS = 256;
static constexpr int M  = 64;    // tokens per sample (g)
static constexpr int C  = 1024;  // channels
static constexpr int NT = 8;     // subtiles per block
static constexpr int SC = 32;    // subtile c-width
static constexpr int NB = 4;     // tin ring depth

__device__ int g_idx_is64; // 1 if indices buffer is int64, 0 if int32

// Indices are in [0, 1024). If buffer is LE int64, odd 32-bit words of the
// first 64 indices are all zero; for int32 data P = (1/1024)^64 ~ 0.
// Reads 128 words — in-bounds either way.
__global__ void detect_idx_dtype(const unsigned int* __restrict__ idx_words)
{
    unsigned int acc = 0;
    #pragma unroll
    for (int i = 0; i < 64; i++) acc |= idx_words[2 * i + 1];
    g_idx_is64 = (acc == 0) ? 1 : 0;
}

__global__ __launch_bounds__(128)
void rvae_gather_transpose(const void*  __restrict__ idx_raw,
                           const float* __restrict__ w,
                           float*       __restrict__ out)
{
    const int b   = blockIdx.y;
    const int cqb = blockIdx.x * (NT * SC); // block base channel (256-span)
    const int t   = threadIdx.x;            // 128 threads

    __shared__ __align__(128) float4 tin[NB][M * 8]; // 4 x 8KB, swizzled

    // Gather lanes: c4 = t&7 (float4 col), gb = t>>3 (0..15), g = gb + 16i.
    const int c4 = t & 7;
    const int gb = t >> 3;
    int row[4];
    if (g_idx_is64) {
        #pragma unroll
        for (int i = 0; i < 4; i++)
            row[i] = (int)reinterpret_cast<const long long*>(idx_raw)[b * M + gb + 16 * i];
    } else {
        #pragma unroll
        for (int i = 0; i < 4; i++)
            row[i] = reinterpret_cast<const int*>(idx_raw)[b * M + gb + 16 * i];
    }

    auto gather = [&](int h) {
        const int c0  = cqb + SC * h;
        float4*   buf = tin[h & (NB - 1)];
        #pragma unroll
        for (int i = 0; i < 4; i++) {
            const int g = gb + 16 * i;
            const float*   src = w + (size_t)row[i] * C + c0 + (c4 << 2);
            const uint32_t dst = (uint32_t)__cvta_generic_to_shared(
                &buf[g * 8 + (c4 ^ ((g >> 2) & 7))]);
            asm volatile("cp.async.cg.shared.global [%0], [%1], 16;"
                         :: "r"(dst), "l"(src) : "memory");
        }
        asm volatile("cp.async.commit_group;" ::: "memory");
    };

    gather(0);
    gather(1);
    gather(2);
    gather(3);

    // Transpose unit: 4g x 4c. ub = g-quad (0..15), uc = c-quad (0..7).
    const int ub = t & 15;
    const int uc = t >> 4;
    const int sc = uc ^ (ub & 7); // swizzled tin column ((4ub+k)>>2 & 7 == ub&7)

    #pragma unroll
    for (int h = 0; h < NT; h++) {
        // EXACT accounting: committed = 4 + clamp(h-1,0,4); need tiles 0..h
        // complete -> allow committed-(h+1) pending groups.
        const int allow = (h == 0) ? 3 : (h <= 5) ? 2 : (h == 6) ? 1 : 0;
        if (allow == 3)      asm volatile("cp.async.wait_group 3;" ::: "memory");
        else if (allow == 2) asm volatile("cp.async.wait_group 2;" ::: "memory");
        else if (allow == 1) asm volatile("cp.async.wait_group 1;" ::: "memory");
        else                 asm volatile("cp.async.wait_group 0;" ::: "memory");
        __syncthreads(); // publishes tile h to all; proves tile h-1 consumed

        // Buffer (h+3)%4 == (h-1)%4 is free now: refill for tile h+3.
        if (h >= 1 && h + 3 < NT) gather(h + 3);

        const float4* ti = tin[h & (NB - 1)];
        const float4 r0 = ti[(4 * ub + 0) * 8 + sc];
        const float4 r1 = ti[(4 * ub + 1) * 8 + sc];
        const float4 r2 = ti[(4 * ub + 2) * 8 + sc];
        const float4 r3 = ti[(4 * ub + 3) * 8 + sc];

        // out[b, cqb + SC*h + 4*uc + j, 4*ub + k]: two contiguous 256B
        // segments per warp STG -> fully coalesced.
        float* ob = out + (size_t)b * (C * M)
                        + (size_t)(cqb + SC * h) * M + 4 * ub;
        *reinterpret_cast<float4*>(ob + (4 * uc + 0) * M) = float4{r0.x, r1.x, r2.x, r3.x};
        *reinterpret_cast<float4*>(ob + (4 * uc + 1) * M) = float4{r0.y, r1.y, r2.y, r3.y};
        *reinterpret_cast<float4*>(ob + (4 * uc + 2) * M) = float4{r0.z, r1.z, r2.z, r3.z};
        *reinterpret_cast<float4*>(ob + (4 * uc + 3) * M) = float4{r0.w, r1.w, r2.w, r3.w};
    }
}

extern "C" void kernel_launch(void* const* d_in, const int* in_sizes, int n_in,
                              void* d_out, int out_size)
{
    // indices: 16384 elements; weight: 1048576 elements (fp32)
    const void*  idx;
    const float* w;
    if (in_sizes[0] == BS * M) {
        idx = d_in[0];
        w   = (const float*)d_in[1];
    } else {
        idx = d_in[1];
        w   = (const float*)d_in[0];
    }

    detect_idx_dtype<<<1, 1>>>((const unsigned int*)idx);

    dim3 grid(C / (NT * SC), BS); // (4, 256) = 1024 blocks ~ one wave
    rvae_gather_transpose<<<grid, 128>>>(idx, w, (float*)d_out);
}